// round 6
// baseline (speedup 1.0000x reference)
#include <cuda_runtime.h>
#include <math.h>
#include <stdint.h>

#define BB 256
#define DD 4096
#define TT 19

// ---------------- static device scratch ------------------------------------
__device__ float g_grad[BB * DD];                     // 4 MB  grad_x = xW + b
__device__ signed char g_As8[BB * DD];                // 1 MB  x as s8
__device__ signed char g_Bq[3][(size_t)DD * DD];      // 48 MB W digit planes

// ---------------------------------------------------------------------------
// conv_w: W fp32 -> 3 balanced s8 digit planes of rint(W * 2^26).
// ---------------------------------------------------------------------------
union B8 { signed char c[8]; uint2 u; };

__global__ void __launch_bounds__(256) conv_w(const float* __restrict__ W)
{
    size_t e = ((size_t)blockIdx.x * 256 + threadIdx.x) * 8;
    float4 a = *reinterpret_cast<const float4*>(W + e);
    float4 b = *reinterpret_cast<const float4*>(W + e + 4);
    float w[8] = {a.x, a.y, a.z, a.w, b.x, b.y, b.z, b.w};
    B8 p0, p1, p2;
#pragma unroll
    for (int i = 0; i < 8; i++) {
        int v = __float2int_rn(w[i] * 67108864.0f);
        v = max(-8000000, min(8000000, v));
        int d0 = ((v + 128) & 255) - 128; v = (v - d0) >> 8;
        int d1 = ((v + 128) & 255) - 128; v = (v - d1) >> 8;
        p0.c[i] = (signed char)d0;
        p1.c[i] = (signed char)d1;
        p2.c[i] = (signed char)v;
    }
    *reinterpret_cast<uint2*>(&g_Bq[0][e]) = p0.u;
    *reinterpret_cast<uint2*>(&g_Bq[1][e]) = p1.u;
    *reinterpret_cast<uint2*>(&g_Bq[2][e]) = p2.u;
}

__global__ void __launch_bounds__(256) conv_a(const float* __restrict__ x)
{
    size_t e = ((size_t)blockIdx.x * 256 + threadIdx.x) * 8;
    float4 a = *reinterpret_cast<const float4*>(x + e);
    float4 b = *reinterpret_cast<const float4*>(x + e + 4);
    float w[8] = {a.x, a.y, a.z, a.w, b.x, b.y, b.z, b.w};
    B8 p;
#pragma unroll
    for (int i = 0; i < 8; i++) p.c[i] = (signed char)(w[i] > 0.5f ? 1 : 0);
    *reinterpret_cast<uint2*>(&g_As8[e]) = p.u;
}

// ---------------------------------------------------------------------------
// Fused int8 tensor-core GEMM over 3 digit planes (K=12288), radix-256
// accumulator scaling at plane boundaries. BK=128B, 4-stage cp.async,
// ONE syncthreads per iteration. 8 warps, warp tile 32x32.
// ---------------------------------------------------------------------------
#define AST (128 * 144)        // 18432
#define BST (64 * 144)         // 9216
#define STB (AST + BST)        // 27648
#define GSMEM (4 * STB)        // 110592
#define KITERS 96              // 3 planes * 32 chunks of K=128

__device__ __forceinline__ uint32_t smem_u32(const void* p) {
    uint32_t a;
    asm("{ .reg .u64 t; cvta.to.shared.u64 t, %1; cvt.u32.u64 %0, t; }" : "=r"(a) : "l"(p));
    return a;
}
__device__ __forceinline__ void cpa16(uint32_t dst, const void* src) {
    asm volatile("cp.async.cg.shared.global [%0], [%1], 16;" :: "r"(dst), "l"(src));
}
__device__ __forceinline__ void ldm4(uint32_t& r0, uint32_t& r1, uint32_t& r2, uint32_t& r3,
                                     uint32_t addr) {
    asm volatile("ldmatrix.sync.aligned.m8n8.x4.shared.b16 {%0,%1,%2,%3}, [%4];"
                 : "=r"(r0), "=r"(r1), "=r"(r2), "=r"(r3) : "r"(addr));
}
__device__ __forceinline__ void mma_s8(int* d, const uint32_t* aa, const uint32_t* bb) {
    asm volatile("mma.sync.aligned.m16n8k32.row.col.s32.s8.s8.s32 "
                 "{%0,%1,%2,%3}, {%4,%5,%6,%7}, {%8,%9}, {%0,%1,%2,%3};"
                 : "+r"(d[0]), "+r"(d[1]), "+r"(d[2]), "+r"(d[3])
                 : "r"(aa[0]), "r"(aa[1]), "r"(aa[2]), "r"(aa[3]), "r"(bb[0]), "r"(bb[1]));
}

__global__ void __launch_bounds__(256, 1) gemm_i8(const float* __restrict__ bv)
{
    extern __shared__ __align__(128) char dsm[];
    const uint32_t sbase = smem_u32(dsm);

    const int tid = threadIdx.x;
    const int wid = tid >> 5;
    const int lane = tid & 31;
    const int nt = blockIdx.x;         // 0..63
    const int mt = blockIdx.y;         // 0..1
    const int wm = wid & 3;
    const int wn = wid >> 2;
    const int gp = lane >> 2;
    const int t4 = lane & 3;

    int acc[2][4][4];
#pragma unroll
    for (int i = 0; i < 2; i++)
#pragma unroll
        for (int j = 0; j < 4; j++)
#pragma unroll
            for (int q = 0; q < 4; q++) acc[i][j][q] = 0;

    auto load_stage = [&](int s, int it) {
        const int plane = 2 - (it >> 5);       // d2 first, then d1, d0
        const int k0 = (it & 31) * 128;
        const signed char* Bp = g_Bq[0] + (size_t)plane * ((size_t)DD * DD);
        uint32_t sb = sbase + s * STB;
        // A: 1024 16B chunks (128 rows x 8)
#pragma unroll
        for (int q = 0; q < 4; q++) {
            int idx = tid + q * 256;
            int row = idx >> 3, col = idx & 7;
            cpa16(sb + row * 144 + col * 16,
                  g_As8 + (size_t)(mt * 128 + row) * DD + k0 + col * 16);
        }
        // B: 512 16B chunks (64 rows x 8)
#pragma unroll
        for (int q = 0; q < 2; q++) {
            int idx = tid + q * 256;
            int row = idx >> 3, col = idx & 7;
            cpa16(sb + AST + row * 144 + col * 16,
                  Bp + (size_t)(nt * 64 + row) * DD + k0 + col * 16);
        }
    };

#pragma unroll
    for (int p = 0; p < 3; p++) {
        load_stage(p, p);
        asm volatile("cp.async.commit_group;");
    }

    const int a_tile = lane >> 3, a_r = lane & 7;
    const int arow_base = wm * 32 + ((a_tile & 1) ? 8 : 0) + a_r;
    const int abyte_base = (a_tile >> 1) ? 16 : 0;
    const int brow_base = wn * 32 + ((a_tile >> 1) ? 8 : 0) + a_r;
    const int bbyte_base = (a_tile & 1) ? 16 : 0;

    for (int i = 0; i < KITERS; i++) {
        asm volatile("cp.async.wait_group 2;");
        __syncthreads();
        // write stage (i+3)&3 == (i-1)&3: all threads finished reading it in
        // iter i-1's compute before reaching this sync (program order).
        if (i + 3 < KITERS) load_stage((i + 3) & 3, i + 3);
        asm volatile("cp.async.commit_group;");

        const uint32_t sb = sbase + (i & 3) * STB;
#pragma unroll
        for (int ks = 0; ks < 4; ks++) {
            uint32_t afr[2][4];
#pragma unroll
            for (int mi = 0; mi < 2; mi++) {
                uint32_t addr = sb + (arow_base + mi * 16) * 144 + abyte_base + ks * 32;
                ldm4(afr[mi][0], afr[mi][1], afr[mi][2], afr[mi][3], addr);
            }
            uint32_t bfr[4][2];
#pragma unroll
            for (int jj = 0; jj < 4; jj += 2) {
                uint32_t addr = sb + AST + (brow_base + jj * 8) * 144 + bbyte_base + ks * 32;
                uint32_t r0, r1, r2, r3;
                ldm4(r0, r1, r2, r3, addr);
                bfr[jj][0] = r0; bfr[jj][1] = r1;
                bfr[jj + 1][0] = r2; bfr[jj + 1][1] = r3;
            }
#pragma unroll
            for (int mi = 0; mi < 2; mi++)
#pragma unroll
                for (int nj = 0; nj < 4; nj++)
                    mma_s8(acc[mi][nj], afr[mi], bfr[nj]);
        }

        // radix scaling at plane boundaries (exact; magnitudes << 2^31)
        if (i == 31 || i == 63) {
#pragma unroll
            for (int mi = 0; mi < 2; mi++)
#pragma unroll
                for (int nj = 0; nj < 4; nj++)
#pragma unroll
                    for (int q = 0; q < 4; q++) acc[mi][nj][q] <<= 8;
        }
    }

    // epilogue: grad = acc * 2^-26 + b
    const double s = 1.0 / 67108864.0;
#pragma unroll
    for (int mi = 0; mi < 2; mi++)
#pragma unroll
        for (int nj = 0; nj < 4; nj++) {
            int row0 = mt * 128 + wm * 32 + mi * 16 + gp;
            int col  = nt * 64 + wn * 32 + nj * 8 + t4 * 2;
            float b0 = bv[col], b1 = bv[col + 1];
            float2 v0, v1;
            v0.x = (float)((double)acc[mi][nj][0] * s + (double)b0);
            v0.y = (float)((double)acc[mi][nj][1] * s + (double)b1);
            v1.x = (float)((double)acc[mi][nj][2] * s + (double)b0);
            v1.y = (float)((double)acc[mi][nj][3] * s + (double)b1);
            *reinterpret_cast<float2*>(g_grad + (size_t)row0 * DD + col) = v0;
            *reinterpret_cast<float2*>(g_grad + (size_t)(row0 + 8) * DD + col) = v1;
        }
}

// ---------------------------------------------------------------------------
// Sampler: per-row Gumbel-max chain, warp-local pruning threshold (one block
// reduction per step), prefetched unif, register-resident ly, MH accept.
// ---------------------------------------------------------------------------
#define NT 256
#define PER (DD / NT)

__global__ void __launch_bounds__(NT, 1)
sampler(const float* __restrict__ x, const float* __restrict__ Wm,
        const float* __restrict__ bv, const float* __restrict__ unif,
        const float* __restrict__ u_accept, const int* __restrict__ radius,
        float* __restrict__ out)
{
    __shared__ float lx[DD];
    __shared__ float ly[DD];
    __shared__ signed char ss[DD];
    __shared__ signed char s0[DD];
    __shared__ float rval[8];
    __shared__ int   ridx[8];
    __shared__ double rdbl[NT];
    __shared__ int         fidx[TT];
    __shared__ signed char fsb[TT];
    __shared__ int   cidx[TT];
    __shared__ float cfac[TT];
    __shared__ int   nchg;
    __shared__ float sh_L;
    __shared__ double sh_sx, sh_sy, sh_sf, sh_sb;
    __shared__ int   sh_acc;

    const int r   = blockIdx.x;
    const int tid = threadIdx.x;
    const int lane = tid & 31;
    const int wrp = tid >> 5;
    const int rad = radius[r];

    // ---- init: lx, signs, score_x, Lmax ----
    double part = 0.0;
    float lmax = 0.f;
#pragma unroll
    for (int i = 0; i < PER; i++) {
        int j = i * NT + tid;
        float l = 0.5f * g_grad[(size_t)r * DD + j];
        lx[j] = l;
        lmax = fmaxf(lmax, fabsf(l));
        float xv = x[(size_t)r * DD + j];
        signed char sgn = (xv > 0.5f) ? (signed char)(-1) : (signed char)1;
        ss[j] = sgn; s0[j] = sgn;
        if (sgn < 0) part += (double)(l + 0.5f * bv[j]);
    }
#pragma unroll
    for (int off = 16; off > 0; off >>= 1)
        lmax = fmaxf(lmax, __shfl_down_sync(0xffffffffu, lmax, off));
    if (lane == 0) rval[wrp] = lmax;
    rdbl[tid] = part; __syncthreads();
    if (tid == 0) {
        float m = rval[0];
        for (int w = 1; w < 8; w++) m = fmaxf(m, rval[w]);
        sh_L = m;
    }
    for (int off = NT / 2; off > 0; off >>= 1) {
        if (tid < off) rdbl[tid] += rdbl[tid + off];
        __syncthreads();
    }
    if (tid == 0) sh_sx = rdbl[0];
    __syncthreads();
    const float Lmax = sh_L;

    // ---- sequential chain with unif prefetch ----
    float4 U0, U1, U2, U3;
    if (rad > 0) {
        const float4* up = reinterpret_cast<const float4*>(unif + (size_t)r * DD);
        U0 = up[tid]; U1 = up[256 + tid]; U2 = up[512 + tid]; U3 = up[768 + tid];
    }
    for (int t = 0; t < rad; t++) {
        float uv[16];
        uv[0] = U0.x; uv[1] = U0.y; uv[2] = U0.z; uv[3] = U0.w;
        uv[4] = U1.x; uv[5] = U1.y; uv[6] = U1.z; uv[7] = U1.w;
        uv[8] = U2.x; uv[9] = U2.y; uv[10] = U2.z; uv[11] = U2.w;
        uv[12] = U3.x; uv[13] = U3.y; uv[14] = U3.z; uv[15] = U3.w;
        // prefetch next step's unif (completes under the work below)
        if (t + 1 < rad) {
            const float4* un = reinterpret_cast<const float4*>(
                unif + ((size_t)(t + 1) * BB + r) * DD);
            U0 = un[tid]; U1 = un[256 + tid]; U2 = un[512 + tid]; U3 = un[768 + tid];
        }
        // per-thread then per-warp argmax of raw u (compare-only)
        float um = -1.f; int im = 0;
#pragma unroll
        for (int i = 0; i < 16; i++) {
            int j = (i >> 2) * 1024 + tid * 4 + (i & 3);
            if (uv[i] > um) { um = uv[i]; im = j; }
        }
#pragma unroll
        for (int off = 16; off > 0; off >>= 1) {
            float v2 = __shfl_down_sync(0xffffffffu, um, off);
            int i2 = __shfl_down_sync(0xffffffffu, im, off);
            if (v2 > um || (v2 == um && i2 < im)) { um = v2; im = i2; }
        }
        // warp-local pruning threshold: any candidate lower-bounds the block
        // winner, so the true winner always survives within its own warp.
        float uth;
        if (lane == 0) {
            float slm = (float)ss[im] * lx[im];
            float gm = -logf(-logf(um));
            uth = expf(-expf(-(gm + slm - Lmax - 0.05f)));
        }
        uth = __shfl_sync(0xffffffffu, uth, 0);

        // pruned pass: logf only for candidates above the warp threshold
        float bvv = -3.4e38f; int bi = 0;
#pragma unroll
        for (int i = 0; i < 16; i++) {
            if (uv[i] >= uth) {
                int j = (i >> 2) * 1024 + tid * 4 + (i & 3);
                float g = -logf(-logf(uv[i]));
                float v = (float)ss[j] * lx[j] + g;
                if (v > bvv) { bvv = v; bi = j; }
            }
        }
#pragma unroll
        for (int off = 16; off > 0; off >>= 1) {
            float v2 = __shfl_down_sync(0xffffffffu, bvv, off);
            int i2 = __shfl_down_sync(0xffffffffu, bi, off);
            if (v2 > bvv || (v2 == bvv && i2 < bi)) { bvv = v2; bi = i2; }
        }
        if (lane == 0) { rval[wrp] = bvv; ridx[wrp] = bi; }
        __syncthreads();
        if (tid < 8) {
            float v = rval[tid]; int i = ridx[tid];
#pragma unroll
            for (int off = 4; off > 0; off >>= 1) {
                float v2 = __shfl_down_sync(0xffu, v, off);
                int i2 = __shfl_down_sync(0xffu, i, off);
                if (v2 > v || (v2 == v && i2 < i)) { v = v2; i = i2; }
            }
            if (tid == 0) { fidx[t] = i; fsb[t] = ss[i]; ss[i] = (signed char)(-ss[i]); }
        }
        __syncthreads();
    }

    // ---- net-changed coordinates ----
    if (tid == 0) {
        int n = 0;
        for (int t = 0; t < rad; t++) {
            int i = fidx[t];
            int found = -1;
            for (int k = 0; k < n; k++) if (cidx[k] == i) { found = k; break; }
            if (found >= 0) { cidx[found] = cidx[n - 1]; n--; }
            else cidx[n++] = i;
        }
        nchg = n;
        for (int k = 0; k < n; k++) cfac[k] = -0.5f * (float)ss[cidx[k]];
    }
    __syncthreads();

    // ---- lyr = lx + sum cfac_k * W[i_k] (registers, pipelined loads) ----
    float lyr[PER];
#pragma unroll
    for (int i = 0; i < PER; i++) lyr[i] = lx[i * NT + tid];
    {
        int nc = nchg;
        if (nc > 0) {
            float cur[PER];
            const float* wr = Wm + (size_t)cidx[0] * DD;
#pragma unroll
            for (int i = 0; i < PER; i++) cur[i] = wr[i * NT + tid];
            for (int k = 0; k < nc; k++) {
                float nxt[PER];
                if (k + 1 < nc) {
                    const float* w2 = Wm + (size_t)cidx[k + 1] * DD;
#pragma unroll
                    for (int i = 0; i < PER; i++) nxt[i] = w2[i * NT + tid];
                }
                float f = cfac[k];
#pragma unroll
                for (int i = 0; i < PER; i++) lyr[i] = fmaf(f, cur[i], lyr[i]);
#pragma unroll
                for (int i = 0; i < PER; i++) cur[i] = nxt[i];
            }
        }
    }
#pragma unroll
    for (int i = 0; i < PER; i++) ly[i * NT + tid] = lyr[i];

    // ---- score_y + base lse sums ----
    double psy = 0.0, psf = 0.0, psb = 0.0;
#pragma unroll
    for (int i = 0; i < PER; i++) {
        int j = i * NT + tid;
        float lyj = lyr[i], lxj = lx[j];
        if (ss[j] < 0) psy += (double)(lyj + 0.5f * bv[j]);
        psf += (double)expf((float)s0[j] * lxj);
        psb += (double)expf((float)ss[j] * lyj);
    }
    rdbl[tid] = psy; __syncthreads();
    for (int off = NT / 2; off > 0; off >>= 1) { if (tid < off) rdbl[tid] += rdbl[tid + off]; __syncthreads(); }
    if (tid == 0) sh_sy = rdbl[0];
    __syncthreads();
    rdbl[tid] = psf; __syncthreads();
    for (int off = NT / 2; off > 0; off >>= 1) { if (tid < off) rdbl[tid] += rdbl[tid + off]; __syncthreads(); }
    if (tid == 0) sh_sf = rdbl[0];
    __syncthreads();
    rdbl[tid] = psb; __syncthreads();
    for (int off = NT / 2; off > 0; off >>= 1) { if (tid < off) rdbl[tid] += rdbl[tid + off]; __syncthreads(); }
    if (tid == 0) sh_sb = rdbl[0];
    __syncthreads();

    // ---- serial accept math (incremental lse walks) ----
    if (tid == 0) {
        double S = sh_sf, lf = 0.0;
        for (int t = 0; t < rad; t++) {
            int i = fidx[t]; float sb = (float)fsb[t]; float l = lx[i];
            lf += (double)(sb * l) - log(S);
            S += exp((double)(-sb * l)) - exp((double)(sb * l));
        }
        lf += sh_sx;

        double Sb = sh_sb, lb = 0.0;
        for (int t = rad - 1; t >= 0; t--) {
            int i = fidx[t]; float sb = (float)fsb[t]; float l = ly[i];
            lb += (double)(-sb * l) - log(Sb);
            Sb += exp((double)(sb * l)) - exp((double)(-sb * l));
        }
        lb += sh_sy;

        float ratio = expf((float)(lb - lf));
        sh_acc = (ratio >= u_accept[r]) ? 1 : 0;
    }
    __syncthreads();

    int acc = sh_acc;
#pragma unroll
    for (int i = 0; i < PER; i++) {
        int j = i * NT + tid;
        float yv = (ss[j] < 0) ? 1.f : 0.f;
        float xv = (s0[j] < 0) ? 1.f : 0.f;
        out[(size_t)r * DD + j] = acc ? yv : xv;
    }
}

// ---------------------------------------------------------------------------
extern "C" void kernel_launch(void* const* d_in, const int* in_sizes, int n_in,
                              void* d_out, int out_size)
{
    (void)in_sizes; (void)n_in; (void)out_size;
    const float* x    = (const float*)d_in[0];
    const float* Wm   = (const float*)d_in[1];
    const float* bv   = (const float*)d_in[2];
    const float* unif = (const float*)d_in[3];
    const float* ua   = (const float*)d_in[4];
    const int*   rad  = (const int*)d_in[5];
    float* out = (float*)d_out;

    static int attr_done = 0;
    if (!attr_done) {
        cudaFuncSetAttribute(gemm_i8, cudaFuncAttributeMaxDynamicSharedMemorySize, GSMEM);
        attr_done = 1;
    }

    conv_w<<<8192, 256>>>(Wm);
    conv_a<<<512, 256>>>(x);
    gemm_i8<<<dim3(64, 2), 256, GSMEM>>>(bv);
    sampler<<<BB, NT>>>(x, Wm, bv, unif, ua, rad, out);
}

// round 7
// speedup vs baseline: 1.2763x; 1.2763x over previous
#include <cuda_runtime.h>
#include <math.h>
#include <stdint.h>

#define BB 256
#define DD 4096
#define TT 19

// ---------------- static device scratch ------------------------------------
__device__ float g_grad[BB * DD];                     // 4 MB  grad_x = xW + b
__device__ signed char g_As8[BB * DD];                // 1 MB  x as s8
__device__ signed char g_Bq[3][(size_t)DD * DD];      // 48 MB W digit planes

// ---------------------------------------------------------------------------
// conv_w: W fp32 -> 3 balanced s8 digit planes of rint(W * 2^26).
// ---------------------------------------------------------------------------
union B8 { signed char c[8]; uint2 u; };

__global__ void __launch_bounds__(256) conv_w(const float* __restrict__ W)
{
    size_t e = ((size_t)blockIdx.x * 256 + threadIdx.x) * 8;
    float4 a = *reinterpret_cast<const float4*>(W + e);
    float4 b = *reinterpret_cast<const float4*>(W + e + 4);
    float w[8] = {a.x, a.y, a.z, a.w, b.x, b.y, b.z, b.w};
    B8 p0, p1, p2;
#pragma unroll
    for (int i = 0; i < 8; i++) {
        int v = __float2int_rn(w[i] * 67108864.0f);
        v = max(-8000000, min(8000000, v));
        int d0 = ((v + 128) & 255) - 128; v = (v - d0) >> 8;
        int d1 = ((v + 128) & 255) - 128; v = (v - d1) >> 8;
        p0.c[i] = (signed char)d0;
        p1.c[i] = (signed char)d1;
        p2.c[i] = (signed char)v;
    }
    *reinterpret_cast<uint2*>(&g_Bq[0][e]) = p0.u;
    *reinterpret_cast<uint2*>(&g_Bq[1][e]) = p1.u;
    *reinterpret_cast<uint2*>(&g_Bq[2][e]) = p2.u;
}

__global__ void __launch_bounds__(256) conv_a(const float* __restrict__ x)
{
    size_t e = ((size_t)blockIdx.x * 256 + threadIdx.x) * 8;
    float4 a = *reinterpret_cast<const float4*>(x + e);
    float4 b = *reinterpret_cast<const float4*>(x + e + 4);
    float w[8] = {a.x, a.y, a.z, a.w, b.x, b.y, b.z, b.w};
    B8 p;
#pragma unroll
    for (int i = 0; i < 8; i++) p.c[i] = (signed char)(w[i] > 0.5f ? 1 : 0);
    *reinterpret_cast<uint2*>(&g_As8[e]) = p.u;
}

// ---------------------------------------------------------------------------
// 16-warp K-split int8 tensor-core GEMM over 3 digit planes.
// Group 0 (warps 0-7):  plane d2 (32 chunks, <<16) + d0 chunks 0-15.
// Group 1 (warps 8-15): plane d1 (32 chunks, <<8)  + d0 chunks 16-31.
// total = accG0 + accG1 = 2^16*S2 + 2^8*S1 + S0  (exact).
// Each group: independent 4-stage cp.async pipeline, named-barrier synced.
// ---------------------------------------------------------------------------
#define AST (128 * 144)        // 18432
#define BST (64 * 144)         // 9216
#define STB (AST + BST)        // 27648
#define GRP_SMEM (4 * STB)     // 110592 per group
#define GSMEM (2 * GRP_SMEM)   // 221184
#define GITERS 48

__device__ __forceinline__ uint32_t smem_u32(const void* p) {
    uint32_t a;
    asm("{ .reg .u64 t; cvta.to.shared.u64 t, %1; cvt.u32.u64 %0, t; }" : "=r"(a) : "l"(p));
    return a;
}
__device__ __forceinline__ void cpa16(uint32_t dst, const void* src) {
    asm volatile("cp.async.cg.shared.global [%0], [%1], 16;" :: "r"(dst), "l"(src));
}
__device__ __forceinline__ void ldm4(uint32_t& r0, uint32_t& r1, uint32_t& r2, uint32_t& r3,
                                     uint32_t addr) {
    asm volatile("ldmatrix.sync.aligned.m8n8.x4.shared.b16 {%0,%1,%2,%3}, [%4];"
                 : "=r"(r0), "=r"(r1), "=r"(r2), "=r"(r3) : "r"(addr));
}
__device__ __forceinline__ void mma_s8(int* d, const uint32_t* aa, const uint32_t* bb) {
    asm volatile("mma.sync.aligned.m16n8k32.row.col.s32.s8.s8.s32 "
                 "{%0,%1,%2,%3}, {%4,%5,%6,%7}, {%8,%9}, {%0,%1,%2,%3};"
                 : "+r"(d[0]), "+r"(d[1]), "+r"(d[2]), "+r"(d[3])
                 : "r"(aa[0]), "r"(aa[1]), "r"(aa[2]), "r"(aa[3]), "r"(bb[0]), "r"(bb[1]));
}
__device__ __forceinline__ void gbar(int id) {
    asm volatile("bar.sync %0, %1;" :: "r"(id), "r"(256) : "memory");
}

__global__ void __launch_bounds__(512, 1) gemm_i8(const float* __restrict__ bv)
{
    extern __shared__ __align__(128) char dsm[];
    const uint32_t sbase = smem_u32(dsm);

    const int tid512 = threadIdx.x;
    const int g = tid512 >> 8;         // group 0 / 1
    const int tid = tid512 & 255;      // group-local tid
    const int wid = tid >> 5;
    const int lane = tid & 31;
    const int nt = blockIdx.x;         // 0..63
    const int mt = blockIdx.y;         // 0..1
    const int wm = wid & 3;
    const int wn = wid >> 2;
    const int gp = lane >> 2;
    const int t4 = lane & 3;
    const uint32_t gbase = sbase + (uint32_t)g * GRP_SMEM;

    int acc[2][4][4];
#pragma unroll
    for (int i = 0; i < 2; i++)
#pragma unroll
        for (int j = 0; j < 4; j++)
#pragma unroll
            for (int q = 0; q < 4; q++) acc[i][j][q] = 0;

    auto load_stage = [&](int s, int it) {
        // group 0: d2 chunks 0-31, then d0 chunks 0-15
        // group 1: d1 chunks 0-31, then d0 chunks 16-31
        int plane, chunk;
        if (g == 0) { plane = (it < 32) ? 2 : 0; chunk = (it < 32) ? it : it - 32; }
        else        { plane = (it < 32) ? 1 : 0; chunk = (it < 32) ? it : it - 16; }
        const int k0 = chunk * 128;
        const signed char* Bp = g_Bq[0] + (size_t)plane * ((size_t)DD * DD);
        uint32_t sb = gbase + (uint32_t)s * STB;
#pragma unroll
        for (int q = 0; q < 4; q++) {
            int idx = tid + q * 256;
            int row = idx >> 3, col = idx & 7;
            cpa16(sb + row * 144 + col * 16,
                  g_As8 + (size_t)(mt * 128 + row) * DD + k0 + col * 16);
        }
#pragma unroll
        for (int q = 0; q < 2; q++) {
            int idx = tid + q * 256;
            int row = idx >> 3, col = idx & 7;
            cpa16(sb + AST + row * 144 + col * 16,
                  Bp + (size_t)(nt * 64 + row) * DD + k0 + col * 16);
        }
    };

#pragma unroll
    for (int p = 0; p < 3; p++) {
        load_stage(p, p);
        asm volatile("cp.async.commit_group;");
    }

    const int a_tile = lane >> 3, a_r = lane & 7;
    const int arow_base = wm * 32 + ((a_tile & 1) ? 8 : 0) + a_r;
    const int abyte_base = (a_tile >> 1) ? 16 : 0;
    const int brow_base = wn * 32 + ((a_tile >> 1) ? 8 : 0) + a_r;
    const int bbyte_base = (a_tile & 1) ? 16 : 0;

    for (int i = 0; i < GITERS; i++) {
        asm volatile("cp.async.wait_group 2;");
        gbar(g + 1);
        if (i + 3 < GITERS) load_stage((i + 3) & 3, i + 3);
        asm volatile("cp.async.commit_group;");

        const uint32_t sb = gbase + (uint32_t)(i & 3) * STB;
#pragma unroll
        for (int ks = 0; ks < 4; ks++) {
            uint32_t afr[2][4];
#pragma unroll
            for (int mi = 0; mi < 2; mi++) {
                uint32_t addr = sb + (arow_base + mi * 16) * 144 + abyte_base + ks * 32;
                ldm4(afr[mi][0], afr[mi][1], afr[mi][2], afr[mi][3], addr);
            }
            uint32_t bfr[4][2];
#pragma unroll
            for (int jj = 0; jj < 4; jj += 2) {
                uint32_t addr = sb + AST + (brow_base + jj * 8) * 144 + bbyte_base + ks * 32;
                uint32_t r0, r1, r2, r3;
                ldm4(r0, r1, r2, r3, addr);
                bfr[jj][0] = r0; bfr[jj][1] = r1;
                bfr[jj + 1][0] = r2; bfr[jj + 1][1] = r3;
            }
#pragma unroll
            for (int mi = 0; mi < 2; mi++)
#pragma unroll
                for (int nj = 0; nj < 4; nj++)
                    mma_s8(acc[mi][nj], afr[mi], bfr[nj]);
        }

        // radix scaling at the group's plane boundary (exact; headroom >= 8 sigma)
        if (i == 31) {
            const int sh = (g == 0) ? 16 : 8;
#pragma unroll
            for (int mi = 0; mi < 2; mi++)
#pragma unroll
                for (int nj = 0; nj < 4; nj++)
#pragma unroll
                    for (int q = 0; q < 4; q++) acc[mi][nj][q] <<= sh;
        }
    }

    // ---- handoff: group1 -> smem (dead stage area), group0 adds + epilogue --
    __syncthreads();
    if (g == 1) {
#pragma unroll
        for (int mi = 0; mi < 2; mi++)
#pragma unroll
            for (int nj = 0; nj < 4; nj++) {
                int row0 = wm * 32 + mi * 16 + gp;
                int col  = wn * 32 + nj * 8 + t4 * 2;
                int* sp = reinterpret_cast<int*>(dsm);
                *reinterpret_cast<int2*>(sp + row0 * 64 + col) =
                    make_int2(acc[mi][nj][0], acc[mi][nj][1]);
                *reinterpret_cast<int2*>(sp + (row0 + 8) * 64 + col) =
                    make_int2(acc[mi][nj][2], acc[mi][nj][3]);
            }
    }
    __syncthreads();
    if (g == 0) {
        const double s = 1.0 / 67108864.0;
        const int* sp = reinterpret_cast<const int*>(dsm);
#pragma unroll
        for (int mi = 0; mi < 2; mi++)
#pragma unroll
            for (int nj = 0; nj < 4; nj++) {
                int lrow = wm * 32 + mi * 16 + gp;
                int col  = wn * 32 + nj * 8 + t4 * 2;
                int2 o0 = *reinterpret_cast<const int2*>(sp + lrow * 64 + col);
                int2 o1 = *reinterpret_cast<const int2*>(sp + (lrow + 8) * 64 + col);
                int row0 = mt * 128 + lrow;
                int gcol = nt * 64 + col;
                float b0 = bv[gcol], b1 = bv[gcol + 1];
                float2 v0, v1;
                v0.x = (float)((double)(acc[mi][nj][0] + o0.x) * s + (double)b0);
                v0.y = (float)((double)(acc[mi][nj][1] + o0.y) * s + (double)b1);
                v1.x = (float)((double)(acc[mi][nj][2] + o1.x) * s + (double)b0);
                v1.y = (float)((double)(acc[mi][nj][3] + o1.y) * s + (double)b1);
                *reinterpret_cast<float2*>(g_grad + (size_t)row0 * DD + gcol) = v0;
                *reinterpret_cast<float2*>(g_grad + (size_t)(row0 + 8) * DD + gcol) = v1;
            }
    }
}

// ---------------------------------------------------------------------------
// Sampler: per-row Gumbel-max chain (block-tight pruning threshold, as R4),
// prefetched unif, register-pipelined grad_y update, MH accept.
// ---------------------------------------------------------------------------
#define NT 256
#define PER (DD / NT)

__global__ void __launch_bounds__(NT, 1)
sampler(const float* __restrict__ x, const float* __restrict__ Wm,
        const float* __restrict__ bv, const float* __restrict__ unif,
        const float* __restrict__ u_accept, const int* __restrict__ radius,
        float* __restrict__ out)
{
    __shared__ float lx[DD];
    __shared__ float ly[DD];
    __shared__ signed char ss[DD];
    __shared__ signed char s0[DD];
    __shared__ float rval[8];
    __shared__ int   ridx[8];
    __shared__ double rdbl[NT];
    __shared__ int         fidx[TT];
    __shared__ signed char fsb[TT];
    __shared__ int   cidx[TT];
    __shared__ float cfac[TT];
    __shared__ int   nchg;
    __shared__ float sh_L;
    __shared__ double sh_sx, sh_sy, sh_sf, sh_sb;
    __shared__ int   sh_acc;

    const int r   = blockIdx.x;
    const int tid = threadIdx.x;
    const int lane = tid & 31;
    const int wrp = tid >> 5;
    const int rad = radius[r];

    // ---- init: lx, signs, score_x, Lmax ----
    double part = 0.0;
    float lmax = 0.f;
#pragma unroll
    for (int i = 0; i < PER; i++) {
        int j = i * NT + tid;
        float l = 0.5f * g_grad[(size_t)r * DD + j];
        lx[j] = l;
        lmax = fmaxf(lmax, fabsf(l));
        float xv = x[(size_t)r * DD + j];
        signed char sgn = (xv > 0.5f) ? (signed char)(-1) : (signed char)1;
        ss[j] = sgn; s0[j] = sgn;
        if (sgn < 0) part += (double)(l + 0.5f * bv[j]);
    }
#pragma unroll
    for (int off = 16; off > 0; off >>= 1)
        lmax = fmaxf(lmax, __shfl_down_sync(0xffffffffu, lmax, off));
    if (lane == 0) rval[wrp] = lmax;
    rdbl[tid] = part; __syncthreads();
    if (tid == 0) {
        float m = rval[0];
        for (int w = 1; w < 8; w++) m = fmaxf(m, rval[w]);
        sh_L = m;
    }
    for (int off = NT / 2; off > 0; off >>= 1) {
        if (tid < off) rdbl[tid] += rdbl[tid + off];
        __syncthreads();
    }
    if (tid == 0) sh_sx = rdbl[0];
    __syncthreads();
    const float Lmax = sh_L;

    // ---- sequential chain with unif prefetch ----
    float4 U0, U1, U2, U3;
    if (rad > 0) {
        const float4* up = reinterpret_cast<const float4*>(unif + (size_t)r * DD);
        U0 = up[tid]; U1 = up[256 + tid]; U2 = up[512 + tid]; U3 = up[768 + tid];
    }
    for (int t = 0; t < rad; t++) {
        float uv[16];
        uv[0] = U0.x; uv[1] = U0.y; uv[2] = U0.z; uv[3] = U0.w;
        uv[4] = U1.x; uv[5] = U1.y; uv[6] = U1.z; uv[7] = U1.w;
        uv[8] = U2.x; uv[9] = U2.y; uv[10] = U2.z; uv[11] = U2.w;
        uv[12] = U3.x; uv[13] = U3.y; uv[14] = U3.z; uv[15] = U3.w;
        // prefetch next step's unif (completes under the work below)
        if (t + 1 < rad) {
            const float4* un = reinterpret_cast<const float4*>(
                unif + ((size_t)(t + 1) * BB + r) * DD);
            U0 = un[tid]; U1 = un[256 + tid]; U2 = un[512 + tid]; U3 = un[768 + tid];
        }
        // block argmax of raw u (compare-only)
        float um = -1.f; int im = 0;
#pragma unroll
        for (int i = 0; i < 16; i++) {
            int j = (i >> 2) * 1024 + tid * 4 + (i & 3);
            if (uv[i] > um) { um = uv[i]; im = j; }
        }
#pragma unroll
        for (int off = 16; off > 0; off >>= 1) {
            float v2 = __shfl_down_sync(0xffffffffu, um, off);
            int i2 = __shfl_down_sync(0xffffffffu, im, off);
            if (v2 > um || (v2 == um && i2 < im)) { um = v2; im = i2; }
        }
        if (lane == 0) { rval[wrp] = um; ridx[wrp] = im; }
        __syncthreads();
        if (tid < 8) {
            float v = rval[tid]; int i = ridx[tid];
#pragma unroll
            for (int off = 4; off > 0; off >>= 1) {
                float v2 = __shfl_down_sync(0xffu, v, off);
                int i2 = __shfl_down_sync(0xffu, i, off);
                if (v2 > v || (v2 == v && i2 < i)) { v = v2; i = i2; }
            }
            if (tid == 0) { rval[0] = v; ridx[0] = i; }
        }
        __syncthreads();
        // block-tight pruning threshold (computed redundantly, in parallel)
        const float umax = rval[0];
        const int imax = ridx[0];
        const float slm = (float)ss[imax] * lx[imax];
        const float gm = -logf(-logf(umax));
        const float uth = expf(-expf(-(gm + slm - Lmax - 0.05f)));

        // pruned pass: logf only for candidates
        float bvv = -3.4e38f; int bi = 0;
#pragma unroll
        for (int i = 0; i < 16; i++) {
            if (uv[i] >= uth) {
                int j = (i >> 2) * 1024 + tid * 4 + (i & 3);
                float g = -logf(-logf(uv[i]));
                float v = (float)ss[j] * lx[j] + g;
                if (v > bvv) { bvv = v; bi = j; }
            }
        }
#pragma unroll
        for (int off = 16; off > 0; off >>= 1) {
            float v2 = __shfl_down_sync(0xffffffffu, bvv, off);
            int i2 = __shfl_down_sync(0xffffffffu, bi, off);
            if (v2 > bvv || (v2 == bvv && i2 < bi)) { bvv = v2; bi = i2; }
        }
        if (lane == 0) { rval[wrp] = bvv; ridx[wrp] = bi; }
        __syncthreads();
        if (tid < 8) {
            float v = rval[tid]; int i = ridx[tid];
#pragma unroll
            for (int off = 4; off > 0; off >>= 1) {
                float v2 = __shfl_down_sync(0xffu, v, off);
                int i2 = __shfl_down_sync(0xffu, i, off);
                if (v2 > v || (v2 == v && i2 < i)) { v = v2; i = i2; }
            }
            if (tid == 0) { fidx[t] = i; fsb[t] = ss[i]; ss[i] = (signed char)(-ss[i]); }
        }
        __syncthreads();
    }

    // ---- net-changed coordinates ----
    if (tid == 0) {
        int n = 0;
        for (int t = 0; t < rad; t++) {
            int i = fidx[t];
            int found = -1;
            for (int k = 0; k < n; k++) if (cidx[k] == i) { found = k; break; }
            if (found >= 0) { cidx[found] = cidx[n - 1]; n--; }
            else cidx[n++] = i;
        }
        nchg = n;
        for (int k = 0; k < n; k++) cfac[k] = -0.5f * (float)ss[cidx[k]];
    }
    __syncthreads();

    // ---- lyr = lx + sum cfac_k * W[i_k] (registers, pipelined loads) ----
    float lyr[PER];
#pragma unroll
    for (int i = 0; i < PER; i++) lyr[i] = lx[i * NT + tid];
    {
        int nc = nchg;
        if (nc > 0) {
            float cur[PER];
            const float* wr = Wm + (size_t)cidx[0] * DD;
#pragma unroll
            for (int i = 0; i < PER; i++) cur[i] = wr[i * NT + tid];
            for (int k = 0; k < nc; k++) {
                float nxt[PER];
                if (k + 1 < nc) {
                    const float* w2 = Wm + (size_t)cidx[k + 1] * DD;
#pragma unroll
                    for (int i = 0; i < PER; i++) nxt[i] = w2[i * NT + tid];
                }
                float f = cfac[k];
#pragma unroll
                for (int i = 0; i < PER; i++) lyr[i] = fmaf(f, cur[i], lyr[i]);
#pragma unroll
                for (int i = 0; i < PER; i++) cur[i] = nxt[i];
            }
        }
    }
#pragma unroll
    for (int i = 0; i < PER; i++) ly[i * NT + tid] = lyr[i];

    // ---- score_y + base lse sums ----
    double psy = 0.0, psf = 0.0, psb = 0.0;
#pragma unroll
    for (int i = 0; i < PER; i++) {
        int j = i * NT + tid;
        float lyj = lyr[i], lxj = lx[j];
        if (ss[j] < 0) psy += (double)(lyj + 0.5f * bv[j]);
        psf += (double)expf((float)s0[j] * lxj);
        psb += (double)expf((float)ss[j] * lyj);
    }
    rdbl[tid] = psy; __syncthreads();
    for (int off = NT / 2; off > 0; off >>= 1) { if (tid < off) rdbl[tid] += rdbl[tid + off]; __syncthreads(); }
    if (tid == 0) sh_sy = rdbl[0];
    __syncthreads();
    rdbl[tid] = psf; __syncthreads();
    for (int off = NT / 2; off > 0; off >>= 1) { if (tid < off) rdbl[tid] += rdbl[tid + off]; __syncthreads(); }
    if (tid == 0) sh_sf = rdbl[0];
    __syncthreads();
    rdbl[tid] = psb; __syncthreads();
    for (int off = NT / 2; off > 0; off >>= 1) { if (tid < off) rdbl[tid] += rdbl[tid + off]; __syncthreads(); }
    if (tid == 0) sh_sb = rdbl[0];
    __syncthreads();

    // ---- serial accept math (incremental lse walks) ----
    if (tid == 0) {
        double S = sh_sf, lf = 0.0;
        for (int t = 0; t < rad; t++) {
            int i = fidx[t]; float sb = (float)fsb[t]; float l = lx[i];
            lf += (double)(sb * l) - log(S);
            S += exp((double)(-sb * l)) - exp((double)(sb * l));
        }
        lf += sh_sx;

        double Sb = sh_sb, lb = 0.0;
        for (int t = rad - 1; t >= 0; t--) {
            int i = fidx[t]; float sb = (float)fsb[t]; float l = ly[i];
            lb += (double)(-sb * l) - log(Sb);
            Sb += exp((double)(sb * l)) - exp((double)(-sb * l));
        }
        lb += sh_sy;

        float ratio = expf((float)(lb - lf));
        sh_acc = (ratio >= u_accept[r]) ? 1 : 0;
    }
    __syncthreads();

    int acc = sh_acc;
#pragma unroll
    for (int i = 0; i < PER; i++) {
        int j = i * NT + tid;
        float yv = (ss[j] < 0) ? 1.f : 0.f;
        float xv = (s0[j] < 0) ? 1.f : 0.f;
        out[(size_t)r * DD + j] = acc ? yv : xv;
    }
}

// ---------------------------------------------------------------------------
extern "C" void kernel_launch(void* const* d_in, const int* in_sizes, int n_in,
                              void* d_out, int out_size)
{
    (void)in_sizes; (void)n_in; (void)out_size;
    const float* x    = (const float*)d_in[0];
    const float* Wm   = (const float*)d_in[1];
    const float* bv   = (const float*)d_in[2];
    const float* unif = (const float*)d_in[3];
    const float* ua   = (const float*)d_in[4];
    const int*   rad  = (const int*)d_in[5];
    float* out = (float*)d_out;

    static int attr_done = 0;
    if (!attr_done) {
        cudaFuncSetAttribute(gemm_i8, cudaFuncAttributeMaxDynamicSharedMemorySize, GSMEM);
        attr_done = 1;
    }

    conv_w<<<8192, 256>>>(Wm);
    conv_a<<<512, 256>>>(x);
    gemm_i8<<<dim3(64, 2), 512, GSMEM>>>(bv);
    sampler<<<BB, NT>>>(x, Wm, bv, unif, ua, rad, out);
}